// round 8
// baseline (speedup 1.0000x reference)
#include <cuda_runtime.h>
#include <math.h>
#include <stdint.h>

// Problem constants
#define S_DIM 512
#define N_DIM 384
#define CM 64
#define CZ 128
#define H_DIM 8
#define C_DIM 32
#define HC 256                  // H*C
#define SN (S_DIM * N_DIM)      // 196608 rows of m
#define M_DIM (S_DIM * C_DIM)   // 16384 = columns of the einsum GEMM

// ---------------- scratch (device globals; no allocation allowed) ----------------
__device__ float g_mn[SN * CM];                    // normalized m (tf32-rounded)
__device__ float g_v[H_DIM * N_DIM * M_DIM];       // v [h][j][s*32+c] (tf32-rounded)
__device__ float g_gate[SN * HC];                  // sigmoid gate [row][k]
__device__ float g_b[H_DIM * N_DIM * N_DIM];       // bias [h][j][i]
__device__ float g_w[H_DIM * N_DIM * N_DIM];       // softmax w [h][i][j] (tf32-rounded)
__device__ float g_wv[H_DIM * N_DIM * M_DIM];      // wv [h][i][s*32+c]
__device__ float g_w1t[CM * HC];                   // W1 tf32-rounded
__device__ float g_w3t[CM * HC];                   // W3 tf32-rounded
__device__ float g_w4t[HC * CM];                   // W4 tf32-rounded
__device__ float g_w2t[H_DIM * CZ];                // W2 transposed [h][k]

// ---------------- helpers ----------------
__device__ __forceinline__ uint32_t f2tf(float x) {
    uint32_t y;
    asm("cvt.rna.tf32.f32 %0, %1;" : "=r"(y) : "f"(x));
    return y;
}
__device__ __forceinline__ float f2tff(float x) { return __uint_as_float(f2tf(x)); }

__device__ __forceinline__ void mma8(float c[4], const uint32_t a[4], const uint32_t b[2]) {
    asm volatile(
        "mma.sync.aligned.m16n8k8.row.col.f32.tf32.tf32.f32 "
        "{%0,%1,%2,%3}, {%4,%5,%6,%7}, {%8,%9}, {%0,%1,%2,%3};\n"
        : "+f"(c[0]), "+f"(c[1]), "+f"(c[2]), "+f"(c[3])
        : "r"(a[0]), "r"(a[1]), "r"(a[2]), "r"(a[3]), "r"(b[0]), "r"(b[1]));
}

// ---------------- K0: round weights to tf32 + transpose W2 ----------------
__global__ void round_weights(const float* __restrict__ W1,
                              const float* __restrict__ W3,
                              const float* __restrict__ W4,
                              const float* __restrict__ W2) {
    int i = blockIdx.x * blockDim.x + threadIdx.x;
    if (i < CM * HC) g_w1t[i] = f2tff(W1[i]);
    if (i < CM * HC) g_w3t[i] = f2tff(W3[i]);
    if (i < HC * CM) g_w4t[i] = f2tff(W4[i]);
    if (i < H_DIM * CZ) {
        int h = i / CZ, k = i % CZ;
        g_w2t[i] = W2[k * H_DIM + h];
    }
}

// ---------------- K1a: LayerNorm over c_m=64, one warp per row ----------------
__global__ void ln_m_kernel(const float* __restrict__ x,
                            const float* __restrict__ gamma,
                            const float* __restrict__ beta) {
    int warp = (blockIdx.x * blockDim.x + threadIdx.x) >> 5;
    int lane = threadIdx.x & 31;
    if (warp >= SN) return;
    const float* row = x + (size_t)warp * CM;
    float a = row[lane];
    float b = row[lane + 32];
    float s = a + b;
    float ss = a * a + b * b;
    #pragma unroll
    for (int o = 16; o > 0; o >>= 1) {
        s  += __shfl_xor_sync(0xffffffffu, s,  o);
        ss += __shfl_xor_sync(0xffffffffu, ss, o);
    }
    float mu  = s * (1.0f / 64.0f);
    float var = ss * (1.0f / 64.0f) - mu * mu;
    float inv = rsqrtf(var + 1e-5f);
    float* out = g_mn + (size_t)warp * CM;
    out[lane]      = f2tff((a - mu) * inv * gamma[lane]      + beta[lane]);
    out[lane + 32] = f2tff((b - mu) * inv * gamma[lane + 32] + beta[lane + 32]);
}

// ============ GEMM machinery: 128 threads, 4 warps (2x2), warp tile 64x64 ============
// As pitch 26: STS 2-way, frag-LDS <=3-way. Interleave: (row,k) -> word (k&3)*2+((k>>2)&1)+(k&8)
struct TS {
    uint32_t As[128][26];
    uint32_t Bs[16][136];
};

__device__ __forceinline__ void mma_tile16w(float acc[4][8][4], const TS* sm,
                                            int wm, int wn, int g, int tig) {
    #pragma unroll
    for (int ks = 0; ks < 16; ks += 8) {
        uint32_t af[4][4], bf[8][2];
        #pragma unroll
        for (int mt = 0; mt < 4; mt++) {
            int r = wm * 64 + mt * 16;
            uint2 ld0 = *(const uint2*)&sm->As[r + g][tig * 2 + ks];
            uint2 ld1 = *(const uint2*)&sm->As[r + g + 8][tig * 2 + ks];
            af[mt][0] = ld0.x; af[mt][2] = ld0.y;
            af[mt][1] = ld1.x; af[mt][3] = ld1.y;
        }
        #pragma unroll
        for (int nt = 0; nt < 8; nt++) {
            int cc = wn * 64 + nt * 8 + g;
            bf[nt][0] = sm->Bs[ks + tig][cc];
            bf[nt][1] = sm->Bs[ks + tig + 4][cc];
        }
        #pragma unroll
        for (int mt = 0; mt < 4; mt++)
            #pragma unroll
            for (int nt = 0; nt < 8; nt++)
                mma8(acc[mt][nt], af[mt], bf[nt]);
    }
}

// stage prefetched regs. Roles (128 threads):
//  A: rows ar=t>>1 and ar+64, cols ah=(t&1)*8 .. +7  (a0,a1 = row ar; a2,a3 = row ar+64)
//  B: row bk=t>>3, cols bm=(t&7)*16 .. +15
__device__ __forceinline__ void stage128(TS* sm, int ar, int ah, int bk, int bm,
                                         const float4& a0, const float4& a1,
                                         const float4& a2, const float4& a3,
                                         const float4& b0, const float4& b1,
                                         const float4& b2, const float4& b3) {
    const float l0[4] = {a0.x, a0.y, a0.z, a0.w};
    const float l1[4] = {a1.x, a1.y, a1.z, a1.w};
    const float l2[4] = {a2.x, a2.y, a2.z, a2.w};
    const float l3[4] = {a3.x, a3.y, a3.z, a3.w};
    #pragma unroll
    for (int j = 0; j < 4; j++) {
        uint2 s0 = {__float_as_uint(l0[j]), __float_as_uint(l1[j])};
        uint2 s1 = {__float_as_uint(l2[j]), __float_as_uint(l3[j])};
        *(uint2*)&sm->As[ar][ah + 2 * j]      = s0;
        *(uint2*)&sm->As[ar + 64][ah + 2 * j] = s1;
    }
    *(float4*)&sm->Bs[bk][bm]      = b0;
    *(float4*)&sm->Bs[bk][bm + 4]  = b1;
    *(float4*)&sm->Bs[bk][bm + 8]  = b2;
    *(float4*)&sm->Bs[bk][bm + 12] = b3;
}

// ---------------- K1b: tf32-MMA GEMM [SN x 64] @ [64 x 512] -> v + gate ----------
__global__ __launch_bounds__(128, 2) void gemm_mw_mma() {
    __shared__ TS sm[2];
    int t = threadIdx.x;
    int lane = t & 31, w = t >> 5;
    int wm = w & 1, wn = w >> 1;
    int g = lane >> 2, tig = lane & 3;
    int i0 = blockIdx.x * 128;
    int cy = blockIdx.y;                          // 0,1 -> W1 halves ; 2,3 -> W3 halves
    const float* B = (cy < 2) ? g_w1t : g_w3t;
    int col0 = (cy & 1) * 128;

    float acc[4][8][4];
    #pragma unroll
    for (int a = 0; a < 4; a++)
        #pragma unroll
        for (int b = 0; b < 8; b++)
            #pragma unroll
            for (int q = 0; q < 4; q++) acc[a][b][q] = 0.0f;

    int ar = t >> 1, ah = (t & 1) * 8;
    int bk = t >> 3, bm = (t & 7) * 16;
    const float* ApL = g_mn + (size_t)(i0 + ar) * CM + ah;
    const float* ApH = ApL + (size_t)64 * CM;
    const float* Bp  = B + (size_t)bk * HC + col0 + bm;

    float4 a0 = *(const float4*)ApL, a1 = *(const float4*)(ApL + 4);
    float4 a2 = *(const float4*)ApH, a3 = *(const float4*)(ApH + 4);
    float4 b0 = *(const float4*)Bp,        b1 = *(const float4*)(Bp + 4);
    float4 b2 = *(const float4*)(Bp + 8),  b3 = *(const float4*)(Bp + 12);

    #pragma unroll 1
    for (int c = 0; c < 4; c++) {
        TS* s = &sm[c & 1];
        stage128(s, ar, ah, bk, bm, a0, a1, a2, a3, b0, b1, b2, b3);
        if (c + 1 < 4) {
            ApL += 16; ApH += 16; Bp += 16 * HC;
            a0 = *(const float4*)ApL; a1 = *(const float4*)(ApL + 4);
            a2 = *(const float4*)ApH; a3 = *(const float4*)(ApH + 4);
            b0 = *(const float4*)Bp;       b1 = *(const float4*)(Bp + 4);
            b2 = *(const float4*)(Bp + 8); b3 = *(const float4*)(Bp + 12);
        }
        __syncthreads();
        mma_tile16w(acc, s, wm, wn, g, tig);
    }

    // epilogue: v (tf32-rounded) or sigmoid gate
    #pragma unroll
    for (int mt = 0; mt < 4; mt++) {
        #pragma unroll
        for (int half = 0; half < 2; half++) {
            int i = i0 + wm * 64 + mt * 16 + g + half * 8;
            int sI = i / N_DIM, n = i % N_DIM;
            #pragma unroll
            for (int nt = 0; nt < 8; nt++) {
                int colp = wn * 64 + nt * 8 + 2 * tig;
                float v0 = acc[mt][nt][half * 2];
                float v1 = acc[mt][nt][half * 2 + 1];
                if (cy < 2) {
                    int colg = cy * 128 + colp;
                    int hh = colg >> 5, cc = colg & 31;
                    float2 st = {f2tff(v0), f2tff(v1)};
                    *(float2*)(g_v + (size_t)(hh * N_DIM + n) * M_DIM + sI * C_DIM + cc) = st;
                } else {
                    float2 st = {1.0f / (1.0f + __expf(-v0)),
                                 1.0f / (1.0f + __expf(-v1))};
                    *(float2*)(g_gate + (size_t)i * HC + (cy - 2) * 128 + colp) = st;
                }
            }
        }
    }
}

// ---------------- K2: warp-per-8-rows LN(z) + @W2t -> b[h][j][i] ----------------
#define LNZ_ROWS 8
__global__ __launch_bounds__(256) void ln_z_warp(const float* __restrict__ z,
                                                 const float* __restrict__ gz,
                                                 const float* __restrict__ bz) {
    int wg = (blockIdx.x * blockDim.x + threadIdx.x) >> 5;
    int lane = threadIdx.x & 31;
    int row0 = wg * LNZ_ROWS;
    if (row0 >= N_DIM * N_DIM) return;

    float4 gm = __ldg((const float4*)(gz + lane * 4));
    float4 bt = __ldg((const float4*)(bz + lane * 4));
    float4 w2[H_DIM];
    #pragma unroll
    for (int h = 0; h < H_DIM; h++)
        w2[h] = __ldg((const float4*)(g_w2t + h * CZ + lane * 4));

    #pragma unroll 1
    for (int r = 0; r < LNZ_ROWS; r++) {
        int row = row0 + r;
        int i = row / N_DIM, j = row % N_DIM;

        float4 x = *(const float4*)(z + (size_t)row * CZ + lane * 4);
        float s  = x.x + x.y + x.z + x.w;
        float ss = x.x * x.x + x.y * x.y + x.z * x.z + x.w * x.w;
        #pragma unroll
        for (int o = 16; o > 0; o >>= 1) {
            s  += __shfl_xor_sync(0xffffffffu, s,  o);
            ss += __shfl_xor_sync(0xffffffffu, ss, o);
        }
        float mu  = s * (1.0f / 128.0f);
        float var = ss * (1.0f / 128.0f) - mu * mu;
        float inv = rsqrtf(var + 1e-5f);

        float zn0 = (x.x - mu) * inv * gm.x + bt.x;
        float zn1 = (x.y - mu) * inv * gm.y + bt.y;
        float zn2 = (x.z - mu) * inv * gm.z + bt.z;
        float zn3 = (x.w - mu) * inv * gm.w + bt.w;

        float acc[H_DIM];
        #pragma unroll
        for (int h = 0; h < H_DIM; h++) {
            acc[h] = zn0 * w2[h].x + zn1 * w2[h].y + zn2 * w2[h].z + zn3 * w2[h].w;
            #pragma unroll
            for (int o = 16; o > 0; o >>= 1)
                acc[h] += __shfl_xor_sync(0xffffffffu, acc[h], o);
        }
        if (lane == 0) {
            #pragma unroll
            for (int h = 0; h < H_DIM; h++)
                g_b[((size_t)h * N_DIM + j) * N_DIM + i] = acc[h];
        }
    }
}

// ---------------- K3: softmax over i (contiguous), write w[h][i][j] tf32 -----------
__global__ void softmax_kernel() {
    __shared__ float redm[4];
    __shared__ float reds[4];
    int j = blockIdx.x;
    int h = blockIdx.y;
    int t = threadIdx.x;
    const float* col = g_b + ((size_t)h * N_DIM + j) * N_DIM;
    float v0 = col[t], v1 = col[t + 128], v2 = col[t + 256];
    float mx = fmaxf(v0, fmaxf(v1, v2));
    #pragma unroll
    for (int o = 16; o > 0; o >>= 1) mx = fmaxf(mx, __shfl_xor_sync(0xffffffffu, mx, o));
    int warp = t >> 5, lane = t & 31;
    if (lane == 0) redm[warp] = mx;
    __syncthreads();
    mx = fmaxf(fmaxf(redm[0], redm[1]), fmaxf(redm[2], redm[3]));
    float e0 = __expf(v0 - mx), e1 = __expf(v1 - mx), e2 = __expf(v2 - mx);
    float sm = e0 + e1 + e2;
    #pragma unroll
    for (int o = 16; o > 0; o >>= 1) sm += __shfl_xor_sync(0xffffffffu, sm, o);
    if (lane == 0) reds[warp] = sm;
    __syncthreads();
    float inv = 1.0f / (reds[0] + reds[1] + reds[2] + reds[3]);
    float* wbase = g_w + (size_t)h * N_DIM * N_DIM + j;
    wbase[(size_t)(t)       * N_DIM] = f2tff(e0 * inv);
    wbase[(size_t)(t + 128) * N_DIM] = f2tff(e1 * inv);
    wbase[(size_t)(t + 256) * N_DIM] = f2tff(e2 * inv);
}

// ---------------- K4: tf32-MMA per-head GEMM  wv_h[i,m] = w_h[i,j] @ v_h[j,m] ------
__global__ __launch_bounds__(128, 2) void gemm_wv_mma() {
    __shared__ TS sm[2];
    int t = threadIdx.x;
    int lane = t & 31, w = t >> 5;
    int wm = w & 1, wn = w >> 1;
    int g = lane >> 2, tig = lane & 3;
    int i0 = blockIdx.x * 128;           // 3 i-tiles (fastest -> v-tile L2 reuse)
    int m0 = blockIdx.y * 128;           // 128 m-tiles
    int h  = blockIdx.z;
    const float* A  = g_w + (size_t)h * N_DIM * N_DIM;   // [i][j]
    const float* Bv = g_v + (size_t)h * N_DIM * M_DIM;   // [j][m]

    float acc[4][8][4];
    #pragma unroll
    for (int a = 0; a < 4; a++)
        #pragma unroll
        for (int b = 0; b < 8; b++)
            #pragma unroll
            for (int q = 0; q < 4; q++) acc[a][b][q] = 0.0f;

    int ar = t >> 1, ah = (t & 1) * 8;
    int bk = t >> 3, bm = (t & 7) * 16;
    const float* ApL = A + (size_t)(i0 + ar) * N_DIM + ah;
    const float* ApH = ApL + (size_t)64 * N_DIM;
    const float* Bp  = Bv + (size_t)bk * M_DIM + m0 + bm;

    float4 a0 = *(const float4*)ApL, a1 = *(const float4*)(ApL + 4);
    float4 a2 = *(const float4*)ApH, a3 = *(const float4*)(ApH + 4);
    float4 b0 = *(const float4*)Bp,        b1 = *(const float4*)(Bp + 4);
    float4 b2 = *(const float4*)(Bp + 8),  b3 = *(const float4*)(Bp + 12);

    #pragma unroll 1
    for (int c = 0; c < 24; c++) {
        TS* s = &sm[c & 1];
        stage128(s, ar, ah, bk, bm, a0, a1, a2, a3, b0, b1, b2, b3);
        if (c + 1 < 24) {
            ApL += 16; ApH += 16; Bp += (size_t)16 * M_DIM;
            a0 = *(const float4*)ApL; a1 = *(const float4*)(ApL + 4);
            a2 = *(const float4*)ApH; a3 = *(const float4*)(ApH + 4);
            b0 = *(const float4*)Bp;       b1 = *(const float4*)(Bp + 4);
            b2 = *(const float4*)(Bp + 8); b3 = *(const float4*)(Bp + 12);
        }
        __syncthreads();
        mma_tile16w(acc, s, wm, wn, g, tig);
    }

    float* dsth = g_wv + (size_t)h * N_DIM * M_DIM;
    #pragma unroll
    for (int mt = 0; mt < 4; mt++) {
        int r = i0 + wm * 64 + mt * 16 + g;
        #pragma unroll
        for (int nt = 0; nt < 8; nt++) {
            int col = m0 + wn * 64 + nt * 8 + 2 * tig;
            float2 v0 = {acc[mt][nt][0], acc[mt][nt][1]};
            float2 v1 = {acc[mt][nt][2], acc[mt][nt][3]};
            *(float2*)(dsth + (size_t)r * M_DIM + col) = v0;
            *(float2*)(dsth + (size_t)(r + 8) * M_DIM + col) = v1;
        }
    }
}

// ---------------- K5: tf32-MMA  out[r,64] = (gate[r,:]*wv_gather[r,:]) @ W4 ----------
__global__ __launch_bounds__(256) void final_mma(float* __restrict__ out) {
    __shared__ uint32_t Os[128][36];
    __shared__ uint32_t Ws[32][72];
    int t = threadIdx.x;
    int lane = t & 31, w = t >> 5;
    int wm = w >> 1, wn = w & 1;
    int g = lane >> 2, tig = lane & 3;
    int r0 = blockIdx.x * 128;

    float acc[2][4][4];
    #pragma unroll
    for (int a = 0; a < 2; a++)
        #pragma unroll
        for (int b = 0; b < 4; b++)
            #pragma unroll
            for (int q = 0; q < 4; q++) acc[a][b][q] = 0.0f;

    for (int k0 = 0; k0 < HC; k0 += 32) {
        int h = k0 >> 5;
        {
            int row = t >> 1, kh = (t & 1) * 16;
            int r = r0 + row;
            int s = r / N_DIM, n = r % N_DIM;
            const float* wvs = g_wv + (size_t)(h * N_DIM + n) * M_DIM + s * C_DIM + kh;
            const float* gts = g_gate + (size_t)r * HC + k0 + kh;
            uint32_t* d = &Os[row][kh];
            #pragma unroll
            for (int u = 0; u < 4; u++) {
                float4 a4 = *(const float4*)(wvs + u * 4);
                float4 g4 = *(const float4*)(gts + u * 4);
                d[u * 4 + 0] = f2tf(a4.x * g4.x);
                d[u * 4 + 1] = f2tf(a4.y * g4.y);
                d[u * 4 + 2] = f2tf(a4.z * g4.z);
                d[u * 4 + 3] = f2tf(a4.w * g4.w);
            }
        }
        {
            int kk = t >> 3, nc = (t & 7) * 8;
            const float* src = g_w4t + (size_t)(k0 + kk) * CM + nc;
            *(float4*)&Ws[kk][nc]     = *(const float4*)src;
            *(float4*)&Ws[kk][nc + 4] = *(const float4*)(src + 4);
        }
        __syncthreads();
        #pragma unroll
        for (int ks = 0; ks < 32; ks += 8) {
            uint32_t af[2][4], bf[4][2];
            #pragma unroll
            for (int mt = 0; mt < 2; mt++) {
                int r = wm * 32 + mt * 16;
                af[mt][0] = Os[r + g][ks + tig];
                af[mt][1] = Os[r + g + 8][ks + tig];
                af[mt][2] = Os[r + g][ks + tig + 4];
                af[mt][3] = Os[r + g + 8][ks + tig + 4];
            }
            #pragma unroll
            for (int nt = 0; nt < 4; nt++) {
                int cc = wn * 32 + nt * 8 + g;
                bf[nt][0] = Ws[ks + tig][cc];
                bf[nt][1] = Ws[ks + tig + 4][cc];
            }
            #pragma unroll
            for (int mt = 0; mt < 2; mt++)
                #pragma unroll
                for (int nt = 0; nt < 4; nt++)
                    mma8(acc[mt][nt], af[mt], bf[nt]);
        }
        __syncthreads();
    }

    #pragma unroll
    for (int mt = 0; mt < 2; mt++) {
        int r = r0 + wm * 32 + mt * 16 + g;
        #pragma unroll
        for (int nt = 0; nt < 4; nt++) {
            int col = wn * 32 + nt * 8 + 2 * tig;
            float2 v0 = {acc[mt][nt][0], acc[mt][nt][1]};
            float2 v1 = {acc[mt][nt][2], acc[mt][nt][3]};
            *(float2*)(out + (size_t)r * CM + col) = v0;
            *(float2*)(out + (size_t)(r + 8) * CM + col) = v1;
        }
    }
}

// ---------------- launch ----------------
extern "C" void kernel_launch(void* const* d_in, const int* in_sizes, int n_in,
                              void* d_out, int out_size) {
    const float* m_si    = (const float*)d_in[0];
    const float* z_ij    = (const float*)d_in[1];
    const float* gamma_m = (const float*)d_in[2];
    const float* beta_m  = (const float*)d_in[3];
    const float* W1      = (const float*)d_in[4];
    const float* gamma_z = (const float*)d_in[5];
    const float* beta_z  = (const float*)d_in[6];
    const float* W2      = (const float*)d_in[7];
    const float* W3      = (const float*)d_in[8];
    const float* W4      = (const float*)d_in[9];
    float* out = (float*)d_out;

    round_weights<<<(CM * HC + 255) / 256, 256>>>(W1, W3, W4, W2);
    ln_m_kernel<<<SN / 8, 256>>>(m_si, gamma_m, beta_m);
    gemm_mw_mma<<<dim3(SN / 128, 4), 128>>>();
    ln_z_warp<<<(N_DIM * N_DIM) / (8 * LNZ_ROWS), 256>>>(z_ij, gamma_z, beta_z);
    softmax_kernel<<<dim3(N_DIM, H_DIM), 128>>>();
    gemm_wv_mma<<<dim3(N_DIM / 128, M_DIM / 128, H_DIM), 128>>>();
    final_mma<<<SN / 128, 256>>>(out);
}

// round 9
// speedup vs baseline: 1.3270x; 1.3270x over previous
#include <cuda_runtime.h>
#include <math.h>
#include <stdint.h>

// Problem constants
#define S_DIM 512
#define N_DIM 384
#define CM 64
#define CZ 128
#define H_DIM 8
#define C_DIM 32
#define HC 256                  // H*C
#define SN (S_DIM * N_DIM)      // 196608 rows of m
#define M_DIM (S_DIM * C_DIM)   // 16384 = columns of the einsum GEMM

// ---------------- scratch (device globals; no allocation allowed) ----------------
__device__ float g_mn[SN * CM];                    // normalized m (tf32-rounded)
__device__ float g_v[H_DIM * N_DIM * M_DIM];       // v [h][j][s*32+c] (tf32-rounded)
__device__ float g_gate[SN * HC];                  // sigmoid gate [row][k]
__device__ float g_b[H_DIM * N_DIM * N_DIM];       // bias [h][j][i]
__device__ float g_w[H_DIM * N_DIM * N_DIM];       // softmax w [h][i][j] (tf32-rounded)
__device__ float g_wv[H_DIM * N_DIM * M_DIM];      // wv [h][i][s*32+c]
__device__ float g_w1t[CM * HC];                   // W1 tf32-rounded
__device__ float g_w3t[CM * HC];                   // W3 tf32-rounded
__device__ float g_w4t[HC * CM];                   // W4 tf32-rounded
__device__ float g_w2t[H_DIM * CZ];                // W2 transposed [h][k]

// ---------------- helpers ----------------
__device__ __forceinline__ uint32_t f2tf(float x) {
    uint32_t y;
    asm("cvt.rna.tf32.f32 %0, %1;" : "=r"(y) : "f"(x));
    return y;
}
__device__ __forceinline__ float f2tff(float x) { return __uint_as_float(f2tf(x)); }

__device__ __forceinline__ void mma8(float c[4], const uint32_t a[4], const uint32_t b[2]) {
    asm volatile(
        "mma.sync.aligned.m16n8k8.row.col.f32.tf32.tf32.f32 "
        "{%0,%1,%2,%3}, {%4,%5,%6,%7}, {%8,%9}, {%0,%1,%2,%3};\n"
        : "+f"(c[0]), "+f"(c[1]), "+f"(c[2]), "+f"(c[3])
        : "r"(a[0]), "r"(a[1]), "r"(a[2]), "r"(a[3]), "r"(b[0]), "r"(b[1]));
}

__device__ __forceinline__ uint32_t smem_u32(const void* p) {
    uint32_t a;
    asm("{ .reg .u64 t; cvta.to.shared.u64 t, %1; cvt.u32.u64 %0, t; }" : "=r"(a) : "l"(p));
    return a;
}
#define CP16(dst_u32, src_ptr) \
    asm volatile("cp.async.ca.shared.global [%0], [%1], 16;" \
                 :: "r"(dst_u32), "l"(src_ptr) : "memory")
#define CP_COMMIT() asm volatile("cp.async.commit_group;" ::: "memory")
#define CP_WAIT1()  asm volatile("cp.async.wait_group 1;" ::: "memory")
#define CP_WAIT0()  asm volatile("cp.async.wait_group 0;" ::: "memory")

// ---------------- K0: round weights to tf32 + transpose W2 ----------------
__global__ void round_weights(const float* __restrict__ W1,
                              const float* __restrict__ W3,
                              const float* __restrict__ W4,
                              const float* __restrict__ W2) {
    int i = blockIdx.x * blockDim.x + threadIdx.x;
    if (i < CM * HC) g_w1t[i] = f2tff(W1[i]);
    if (i < CM * HC) g_w3t[i] = f2tff(W3[i]);
    if (i < HC * CM) g_w4t[i] = f2tff(W4[i]);
    if (i < H_DIM * CZ) {
        int h = i / CZ, k = i % CZ;
        g_w2t[i] = W2[k * H_DIM + h];
    }
}

// ---------------- K1a: LayerNorm over c_m=64, one warp per row ----------------
__global__ void ln_m_kernel(const float* __restrict__ x,
                            const float* __restrict__ gamma,
                            const float* __restrict__ beta) {
    int warp = (blockIdx.x * blockDim.x + threadIdx.x) >> 5;
    int lane = threadIdx.x & 31;
    if (warp >= SN) return;
    const float* row = x + (size_t)warp * CM;
    float a = row[lane];
    float b = row[lane + 32];
    float s = a + b;
    float ss = a * a + b * b;
    #pragma unroll
    for (int o = 16; o > 0; o >>= 1) {
        s  += __shfl_xor_sync(0xffffffffu, s,  o);
        ss += __shfl_xor_sync(0xffffffffu, ss, o);
    }
    float mu  = s * (1.0f / 64.0f);
    float var = ss * (1.0f / 64.0f) - mu * mu;
    float inv = rsqrtf(var + 1e-5f);
    float* out = g_mn + (size_t)warp * CM;
    out[lane]      = f2tff((a - mu) * inv * gamma[lane]      + beta[lane]);
    out[lane + 32] = f2tff((b - mu) * inv * gamma[lane + 32] + beta[lane + 32]);
}

// ============ GEMM machinery: 256 threads, 8 warps (2x4), warp tile 64x32 ============
// As: plain row-major pitch 20 (cp.async 16B chunks; frag LDS.32 conflict-free).
// Bs: [k][col] pitch 136.
struct TS {
    uint32_t As[128][20];
    uint32_t Bs[16][136];
};

__device__ __forceinline__ void mma_tile16(float acc[4][4][4], const TS* sm,
                                           int wm, int wn, int g, int tig) {
    #pragma unroll
    for (int ks = 0; ks < 16; ks += 8) {
        uint32_t af[4][4], bf[4][2];
        #pragma unroll
        for (int mt = 0; mt < 4; mt++) {
            int r = wm * 64 + mt * 16;
            af[mt][0] = sm->As[r + g][ks + tig];
            af[mt][1] = sm->As[r + g + 8][ks + tig];
            af[mt][2] = sm->As[r + g][ks + tig + 4];
            af[mt][3] = sm->As[r + g + 8][ks + tig + 4];
        }
        #pragma unroll
        for (int nt = 0; nt < 4; nt++) {
            int cc = wn * 32 + nt * 8 + g;
            bf[nt][0] = sm->Bs[ks + tig][cc];
            bf[nt][1] = sm->Bs[ks + tig + 4][cc];
        }
        #pragma unroll
        for (int mt = 0; mt < 4; mt++)
            #pragma unroll
            for (int nt = 0; nt < 4; nt++)
                mma8(acc[mt][nt], af[mt], bf[nt]);
    }
}

// cp.async staging. 256 threads. A tile: 128 rows x 16 k (512 16B-chunks, 2/thread).
// B tile: 16 rows x 128 cols (512 16B-chunks, 2/thread).
// lda/ldb in floats. aptr/bptr point at (row0, k0) / (k0, col0) for this chunk.
__device__ __forceinline__ void stage_cp(uint32_t sA, uint32_t sB, int t,
                                         const float* aptr, size_t lda,
                                         const float* bptr, size_t ldb) {
    #pragma unroll
    for (int u = 0; u < 2; u++) {
        int idx = t + u * 256;
        int row = idx >> 2, kc = idx & 3;
        CP16(sA + (row * 20 + kc * 4) * 4, aptr + (size_t)row * lda + kc * 4);
    }
    #pragma unroll
    for (int u = 0; u < 2; u++) {
        int idx = t + u * 256;
        int brow = idx >> 5, bc = idx & 31;
        CP16(sB + (brow * 136 + bc * 4) * 4, bptr + (size_t)brow * ldb + bc * 4);
    }
}

// ---------------- K1b: tf32-MMA GEMM [SN x 64] @ [64 x 512] -> v + gate ----------
__global__ __launch_bounds__(256, 2) void gemm_mw_mma() {
    __shared__ TS sm[2];
    int t = threadIdx.x;
    int lane = t & 31, w = t >> 5;
    int wm = w & 1, wn = w >> 1;
    int g = lane >> 2, tig = lane & 3;
    int i0 = blockIdx.x * 128;
    int cy = blockIdx.y;                          // 0,1 -> W1 halves ; 2,3 -> W3 halves
    const float* B = (cy < 2) ? g_w1t : g_w3t;
    int col0 = (cy & 1) * 128;

    uint32_t sA[2] = {smem_u32(sm[0].As), smem_u32(sm[1].As)};
    uint32_t sB[2] = {smem_u32(sm[0].Bs), smem_u32(sm[1].Bs)};

    float acc[4][4][4];
    #pragma unroll
    for (int a = 0; a < 4; a++)
        #pragma unroll
        for (int b = 0; b < 4; b++)
            #pragma unroll
            for (int q = 0; q < 4; q++) acc[a][b][q] = 0.0f;

    const float* Abase = g_mn + (size_t)i0 * CM;
    const float* Bbase = B + col0;

    stage_cp(sA[0], sB[0], t, Abase, CM, Bbase, HC);
    CP_COMMIT();

    #pragma unroll 1
    for (int c = 0; c < 4; c++) {
        int b = c & 1;
        if (c + 1 < 4)
            stage_cp(sA[1 - b], sB[1 - b], t,
                     Abase + (c + 1) * 16, CM,
                     Bbase + (size_t)(c + 1) * 16 * HC, HC);
        CP_COMMIT();
        if (c + 1 < 4) { CP_WAIT1(); } else { CP_WAIT0(); }
        __syncthreads();
        mma_tile16(acc, &sm[b], wm, wn, g, tig);
        __syncthreads();
    }

    // epilogue: v (tf32-rounded) or sigmoid gate
    #pragma unroll
    for (int mt = 0; mt < 4; mt++) {
        #pragma unroll
        for (int half = 0; half < 2; half++) {
            int i = i0 + wm * 64 + mt * 16 + g + half * 8;
            int s = i / N_DIM, n = i % N_DIM;
            #pragma unroll
            for (int nt = 0; nt < 4; nt++) {
                int colp = wn * 32 + nt * 8 + 2 * tig;
                float v0 = acc[mt][nt][half * 2];
                float v1 = acc[mt][nt][half * 2 + 1];
                if (cy < 2) {
                    int colg = cy * 128 + colp;
                    int hh = colg >> 5, cc = colg & 31;
                    float2 st = {f2tff(v0), f2tff(v1)};
                    *(float2*)(g_v + (size_t)(hh * N_DIM + n) * M_DIM + s * C_DIM + cc) = st;
                } else {
                    float2 st = {1.0f / (1.0f + __expf(-v0)),
                                 1.0f / (1.0f + __expf(-v1))};
                    *(float2*)(g_gate + (size_t)i * HC + (cy - 2) * 128 + colp) = st;
                }
            }
        }
    }
}

// ---------------- K2: warp-per-8-rows LN(z) + @W2t -> b[h][j][i] ----------------
#define LNZ_ROWS 8
__global__ __launch_bounds__(256) void ln_z_warp(const float* __restrict__ z,
                                                 const float* __restrict__ gz,
                                                 const float* __restrict__ bz) {
    int wg = (blockIdx.x * blockDim.x + threadIdx.x) >> 5;
    int lane = threadIdx.x & 31;
    int row0 = wg * LNZ_ROWS;
    if (row0 >= N_DIM * N_DIM) return;

    float4 gm = __ldg((const float4*)(gz + lane * 4));
    float4 bt = __ldg((const float4*)(bz + lane * 4));
    float4 w2[H_DIM];
    #pragma unroll
    for (int h = 0; h < H_DIM; h++)
        w2[h] = __ldg((const float4*)(g_w2t + h * CZ + lane * 4));

    #pragma unroll 1
    for (int r = 0; r < LNZ_ROWS; r++) {
        int row = row0 + r;
        int i = row / N_DIM, j = row % N_DIM;

        float4 x = *(const float4*)(z + (size_t)row * CZ + lane * 4);
        float s  = x.x + x.y + x.z + x.w;
        float ss = x.x * x.x + x.y * x.y + x.z * x.z + x.w * x.w;
        #pragma unroll
        for (int o = 16; o > 0; o >>= 1) {
            s  += __shfl_xor_sync(0xffffffffu, s,  o);
            ss += __shfl_xor_sync(0xffffffffu, ss, o);
        }
        float mu  = s * (1.0f / 128.0f);
        float var = ss * (1.0f / 128.0f) - mu * mu;
        float inv = rsqrtf(var + 1e-5f);

        float zn0 = (x.x - mu) * inv * gm.x + bt.x;
        float zn1 = (x.y - mu) * inv * gm.y + bt.y;
        float zn2 = (x.z - mu) * inv * gm.z + bt.z;
        float zn3 = (x.w - mu) * inv * gm.w + bt.w;

        float acc[H_DIM];
        #pragma unroll
        for (int h = 0; h < H_DIM; h++) {
            acc[h] = zn0 * w2[h].x + zn1 * w2[h].y + zn2 * w2[h].z + zn3 * w2[h].w;
            #pragma unroll
            for (int o = 16; o > 0; o >>= 1)
                acc[h] += __shfl_xor_sync(0xffffffffu, acc[h], o);
        }
        if (lane == 0) {
            #pragma unroll
            for (int h = 0; h < H_DIM; h++)
                g_b[((size_t)h * N_DIM + j) * N_DIM + i] = acc[h];
        }
    }
}

// ---------------- K3: softmax over i (contiguous), write w[h][i][j] tf32 -----------
__global__ void softmax_kernel() {
    __shared__ float redm[4];
    __shared__ float reds[4];
    int j = blockIdx.x;
    int h = blockIdx.y;
    int t = threadIdx.x;
    const float* col = g_b + ((size_t)h * N_DIM + j) * N_DIM;
    float v0 = col[t], v1 = col[t + 128], v2 = col[t + 256];
    float mx = fmaxf(v0, fmaxf(v1, v2));
    #pragma unroll
    for (int o = 16; o > 0; o >>= 1) mx = fmaxf(mx, __shfl_xor_sync(0xffffffffu, mx, o));
    int warp = t >> 5, lane = t & 31;
    if (lane == 0) redm[warp] = mx;
    __syncthreads();
    mx = fmaxf(fmaxf(redm[0], redm[1]), fmaxf(redm[2], redm[3]));
    float e0 = __expf(v0 - mx), e1 = __expf(v1 - mx), e2 = __expf(v2 - mx);
    float sm = e0 + e1 + e2;
    #pragma unroll
    for (int o = 16; o > 0; o >>= 1) sm += __shfl_xor_sync(0xffffffffu, sm, o);
    if (lane == 0) reds[warp] = sm;
    __syncthreads();
    float inv = 1.0f / (reds[0] + reds[1] + reds[2] + reds[3]);
    float* wbase = g_w + (size_t)h * N_DIM * N_DIM + j;
    wbase[(size_t)(t)       * N_DIM] = f2tff(e0 * inv);
    wbase[(size_t)(t + 128) * N_DIM] = f2tff(e1 * inv);
    wbase[(size_t)(t + 256) * N_DIM] = f2tff(e2 * inv);
}

// ---------------- K4: tf32-MMA per-head GEMM  wv_h[i,m] = w_h[i,j] @ v_h[j,m] ------
__global__ __launch_bounds__(256, 2) void gemm_wv_mma() {
    __shared__ TS sm[2];
    int t = threadIdx.x;
    int lane = t & 31, w = t >> 5;
    int wm = w & 1, wn = w >> 1;
    int g = lane >> 2, tig = lane & 3;
    int i0 = blockIdx.x * 128;           // 3 i-tiles (fastest -> v-tile L2 reuse)
    int m0 = blockIdx.y * 128;           // 128 m-tiles
    int h  = blockIdx.z;
    const float* A  = g_w + (size_t)h * N_DIM * N_DIM;   // [i][j]
    const float* Bv = g_v + (size_t)h * N_DIM * M_DIM;   // [j][m]

    uint32_t sA[2] = {smem_u32(sm[0].As), smem_u32(sm[1].As)};
    uint32_t sB[2] = {smem_u32(sm[0].Bs), smem_u32(sm[1].Bs)};

    float acc[4][4][4];
    #pragma unroll
    for (int a = 0; a < 4; a++)
        #pragma unroll
        for (int b = 0; b < 4; b++)
            #pragma unroll
            for (int q = 0; q < 4; q++) acc[a][b][q] = 0.0f;

    const float* Abase = A + (size_t)i0 * N_DIM;
    const float* Bbase = Bv + m0;

    stage_cp(sA[0], sB[0], t, Abase, N_DIM, Bbase, M_DIM);
    CP_COMMIT();

    #pragma unroll 1
    for (int c = 0; c < 24; c++) {
        int b = c & 1;
        if (c + 1 < 24)
            stage_cp(sA[1 - b], sB[1 - b], t,
                     Abase + (c + 1) * 16, N_DIM,
                     Bbase + (size_t)(c + 1) * 16 * M_DIM, M_DIM);
        CP_COMMIT();
        if (c + 1 < 24) { CP_WAIT1(); } else { CP_WAIT0(); }
        __syncthreads();
        mma_tile16(acc, &sm[b], wm, wn, g, tig);
        __syncthreads();
    }

    float* dsth = g_wv + (size_t)h * N_DIM * M_DIM;
    #pragma unroll
    for (int mt = 0; mt < 4; mt++) {
        int r = i0 + wm * 64 + mt * 16 + g;
        #pragma unroll
        for (int nt = 0; nt < 4; nt++) {
            int col = m0 + wn * 32 + nt * 8 + 2 * tig;
            float2 v0 = {acc[mt][nt][0], acc[mt][nt][1]};
            float2 v1 = {acc[mt][nt][2], acc[mt][nt][3]};
            *(float2*)(dsth + (size_t)r * M_DIM + col) = v0;
            *(float2*)(dsth + (size_t)(r + 8) * M_DIM + col) = v1;
        }
    }
}

// ---------------- K5: tf32-MMA  out[r,64] = (gate[r,:]*wv_gather[r,:]) @ W4 ----------
__global__ __launch_bounds__(256) void final_mma(float* __restrict__ out) {
    __shared__ uint32_t Os[128][36];
    __shared__ uint32_t Ws[32][72];
    int t = threadIdx.x;
    int lane = t & 31, w = t >> 5;
    int wm = w >> 1, wn = w & 1;
    int g = lane >> 2, tig = lane & 3;
    int r0 = blockIdx.x * 128;

    float acc[2][4][4];
    #pragma unroll
    for (int a = 0; a < 2; a++)
        #pragma unroll
        for (int b = 0; b < 4; b++)
            #pragma unroll
            for (int q = 0; q < 4; q++) acc[a][b][q] = 0.0f;

    for (int k0 = 0; k0 < HC; k0 += 32) {
        int h = k0 >> 5;
        {
            int row = t >> 1, kh = (t & 1) * 16;
            int r = r0 + row;
            int s = r / N_DIM, n = r % N_DIM;
            const float* wvs = g_wv + (size_t)(h * N_DIM + n) * M_DIM + s * C_DIM + kh;
            const float* gts = g_gate + (size_t)r * HC + k0 + kh;
            uint32_t* d = &Os[row][kh];
            #pragma unroll
            for (int u = 0; u < 4; u++) {
                float4 a4 = *(const float4*)(wvs + u * 4);
                float4 g4 = *(const float4*)(gts + u * 4);
                d[u * 4 + 0] = f2tf(a4.x * g4.x);
                d[u * 4 + 1] = f2tf(a4.y * g4.y);
                d[u * 4 + 2] = f2tf(a4.z * g4.z);
                d[u * 4 + 3] = f2tf(a4.w * g4.w);
            }
        }
        {
            int kk = t >> 3, nc = (t & 7) * 8;
            const float* src = g_w4t + (size_t)(k0 + kk) * CM + nc;
            *(float4*)&Ws[kk][nc]     = *(const float4*)src;
            *(float4*)&Ws[kk][nc + 4] = *(const float4*)(src + 4);
        }
        __syncthreads();
        #pragma unroll
        for (int ks = 0; ks < 32; ks += 8) {
            uint32_t af[2][4], bf[4][2];
            #pragma unroll
            for (int mt = 0; mt < 2; mt++) {
                int r = wm * 32 + mt * 16;
                af[mt][0] = Os[r + g][ks + tig];
                af[mt][1] = Os[r + g + 8][ks + tig];
                af[mt][2] = Os[r + g][ks + tig + 4];
                af[mt][3] = Os[r + g + 8][ks + tig + 4];
            }
            #pragma unroll
            for (int nt = 0; nt < 4; nt++) {
                int cc = wn * 32 + nt * 8 + g;
                bf[nt][0] = Ws[ks + tig][cc];
                bf[nt][1] = Ws[ks + tig + 4][cc];
            }
            #pragma unroll
            for (int mt = 0; mt < 2; mt++)
                #pragma unroll
                for (int nt = 0; nt < 4; nt++)
                    mma8(acc[mt][nt], af[mt], bf[nt]);
        }
        __syncthreads();
    }

    #pragma unroll
    for (int mt = 0; mt < 2; mt++) {
        int r = r0 + wm * 32 + mt * 16 + g;
        #pragma unroll
        for (int nt = 0; nt < 4; nt++) {
            int col = wn * 32 + nt * 8 + 2 * tig;
            float2 v0 = {acc[mt][nt][0], acc[mt][nt][1]};
            float2 v1 = {acc[mt][nt][2], acc[mt][nt][3]};
            *(float2*)(out + (size_t)r * CM + col) = v0;
            *(float2*)(out + (size_t)(r + 8) * CM + col) = v1;
        }
    }
}

// ---------------- launch ----------------
extern "C" void kernel_launch(void* const* d_in, const int* in_sizes, int n_in,
                              void* d_out, int out_size) {
    const float* m_si    = (const float*)d_in[0];
    const float* z_ij    = (const float*)d_in[1];
    const float* gamma_m = (const float*)d_in[2];
    const float* beta_m  = (const float*)d_in[3];
    const float* W1      = (const float*)d_in[4];
    const float* gamma_z = (const float*)d_in[5];
    const float* beta_z  = (const float*)d_in[6];
    const float* W2      = (const float*)d_in[7];
    const float* W3      = (const float*)d_in[8];
    const float* W4      = (const float*)d_in[9];
    float* out = (float*)d_out;

    round_weights<<<(CM * HC + 255) / 256, 256>>>(W1, W3, W4, W2);
    ln_m_kernel<<<SN / 8, 256>>>(m_si, gamma_m, beta_m);
    gemm_mw_mma<<<dim3(SN / 128, 4), 256>>>();
    ln_z_warp<<<(N_DIM * N_DIM) / (8 * LNZ_ROWS), 256>>>(z_ij, gamma_z, beta_z);
    softmax_kernel<<<dim3(N_DIM, H_DIM), 128>>>();
    gemm_wv_mma<<<dim3(N_DIM / 128, M_DIM / 128, H_DIM), 256>>>();
    final_mma<<<SN / 128, 256>>>(out);
}